// round 3
// baseline (speedup 1.0000x reference)
#include <cuda_runtime.h>
#include <cstdint>

// Problem constants
#define B_    256
#define NMAX_ 512
#define H_    256
#define C_    64
#define HID_  512
#define TILE_D 16
#define KB     8
#define NEGV  (-1000000000.0f)

// Scratch (allocation-free rule: device globals)
__device__ float g_base[B_ * HID_];     // per-batch: b1 + src@W1_src + cc@W1_cc
__device__ float g_scores[B_ * NMAX_];  // padded to 512 per batch

// ---- packed f32x2 helpers (Blackwell FFMA2 path) ----
__device__ __forceinline__ void ffma2(unsigned long long& acc,
                                      unsigned long long a,
                                      unsigned long long b) {
    asm("fma.rn.f32x2 %0, %1, %2, %0;" : "+l"(acc) : "l"(a), "l"(b));
}
__device__ __forceinline__ unsigned long long pack2(float lo, float hi) {
    unsigned long long r;
    asm("mov.b64 %0, {%1, %2};" : "=l"(r) : "f"(lo), "f"(hi));
    return r;
}
__device__ __forceinline__ float2 unpack2(unsigned long long v) {
    float2 r;
    asm("mov.b64 {%0, %1}, %2;" : "=f"(r.x), "=f"(r.y) : "l"(v));
    return r;
}

// ============================================================
// Kernel 1: per-batch constant part of layer 1
// base[b][j] = b1[j] + sum_k src[k]*W1[off_src+k][j] + sum_k cc[k]*W1[2H+k][j]
// ============================================================
__global__ void base_kernel(const float* __restrict__ nodes,
                            const float* __restrict__ cc,
                            const float* __restrict__ W1,
                            const float* __restrict__ b1,
                            const int* __restrict__ dirns,
                            const int* __restrict__ ncnt) {
    __shared__ float sS[H_];
    __shared__ float sC[C_];
    int b = blockIdx.x, t = threadIdx.x;
    int nc = ncnt[b];
    const float* src = nodes + ((size_t)b * NMAX_ + (size_t)(nc - 1)) * H_;
    sS[t] = src[t];
    if (t < C_) sC[t] = cc[b * C_ + t];
    __syncthreads();

    // dirn==1: side_a=cand (rows 0..H-1), side_b=src (rows H..2H-1)
    int off_src = (dirns[b] == 1) ? H_ : 0;
    int j = t;
    float a0 = b1[j];
    float a1 = b1[j + 256];
    const float* Wp = W1 + (size_t)off_src * HID_;
#pragma unroll 4
    for (int k = 0; k < H_; k++) {
        float s = sS[k];
        a0 = fmaf(s, Wp[(size_t)k * HID_ + j], a0);
        a1 = fmaf(s, Wp[(size_t)k * HID_ + j + 256], a1);
    }
    const float* Wc = W1 + (size_t)(2 * H_) * HID_;
#pragma unroll 4
    for (int k = 0; k < C_; k++) {
        float s = sC[k];
        a0 = fmaf(s, Wc[(size_t)k * HID_ + j], a0);
        a1 = fmaf(s, Wc[(size_t)k * HID_ + j + 256], a1);
    }
    g_base[b * HID_ + j] = a0;
    g_base[b * HID_ + j + 256] = a1;
}

// ============================================================
// Kernel 2: fused MLP over a 16-row tile of one batch.
//   h1 = relu(cand @ W1_cand + base)          (256 -> 512)
//   score = relu(h1 @ W2 + b2) @ W3 + b3      (512 -> 512 -> 1, h2 never stored)
// Thread map: 4 row-groups x 64 col-groups; per-thread 4 rows x 8 cols,
// columns paired into f32x2 so W pairs come free from LDS.128.
// ============================================================
__global__ void __launch_bounds__(256, 3) mlp_kernel(
    const float* __restrict__ nodes,
    const float* __restrict__ W1,
    const float* __restrict__ W2,
    const float* __restrict__ b2,
    const float* __restrict__ W3,
    const float* __restrict__ b3,
    const int* __restrict__ dirns) {
    extern __shared__ float sm[];
    float* sA   = sm;                         // TILE_D * H_   = 4096 f
    float* sH   = sm + TILE_D * H_;           // TILE_D * HID_ = 8192 f
    float* sW   = sH + TILE_D * HID_;         // KB * HID_     = 4096 f
    float* sRed = sW + KB * HID_;             // TILE_D * 2    =   32 f

    int b  = blockIdx.y;
    int d0 = blockIdx.x * TILE_D;
    int t  = threadIdx.x;
    int rg = t >> 6;        // 0..3
    int cg = t & 63;        // 0..63
    int r0 = rg * 4;
    int c0 = cg * 8;

    // stage cand tile (16 x 256 floats), float4 coalesced
    {
        const float4* src = reinterpret_cast<const float4*>(
            nodes + ((size_t)b * NMAX_ + d0) * H_);
        float4* dst = reinterpret_cast<float4*>(sA);
#pragma unroll
        for (int i = 0; i < (TILE_D * H_ / 4) / 256; i++)
            dst[t + i * 256] = src[t + i * 256];
    }

    int off_cand = (dirns[b] == 1) ? 0 : H_;
    const float* W1c = W1 + (size_t)off_cand * HID_;

    // ---------------- layer 1 ----------------
    unsigned long long acc[4][4];
    {
        const float4* bp =
            reinterpret_cast<const float4*>(g_base + b * HID_ + c0);
        float4 v0 = bp[0], v1 = bp[1];
        unsigned long long p0 = pack2(v0.x, v0.y), p1 = pack2(v0.z, v0.w);
        unsigned long long p2 = pack2(v1.x, v1.y), p3 = pack2(v1.z, v1.w);
#pragma unroll
        for (int i = 0; i < 4; i++) {
            acc[i][0] = p0; acc[i][1] = p1; acc[i][2] = p2; acc[i][3] = p3;
        }
    }

    for (int k0 = 0; k0 < H_; k0 += KB) {
        __syncthreads();  // protect sW reuse (also covers initial sA store)
        {
            const float4* g =
                reinterpret_cast<const float4*>(W1c + (size_t)k0 * HID_);
            float4* dst = reinterpret_cast<float4*>(sW);
#pragma unroll
            for (int i = 0; i < 4; i++) dst[t + i * 256] = g[t + i * 256];
        }
        __syncthreads();
#pragma unroll
        for (int k = 0; k < KB; k++) {
            const ulonglong2* wr =
                reinterpret_cast<const ulonglong2*>(sW + k * HID_ + c0);
            ulonglong2 wA = wr[0], wB = wr[1];
#pragma unroll
            for (int i = 0; i < 4; i++) {
                float a = sA[(r0 + i) * H_ + k0 + k];
                unsigned long long ap = pack2(a, a);
                ffma2(acc[i][0], ap, wA.x);
                ffma2(acc[i][1], ap, wA.y);
                ffma2(acc[i][2], ap, wB.x);
                ffma2(acc[i][3], ap, wB.y);
            }
        }
    }

    // relu -> sH
    __syncthreads();
#pragma unroll
    for (int i = 0; i < 4; i++) {
#pragma unroll
        for (int jp = 0; jp < 4; jp++) {
            float2 v = unpack2(acc[i][jp]);
            sH[(r0 + i) * HID_ + c0 + 2 * jp]     = fmaxf(v.x, 0.f);
            sH[(r0 + i) * HID_ + c0 + 2 * jp + 1] = fmaxf(v.y, 0.f);
        }
    }
    __syncthreads();

    // ---------------- layer 2 ----------------
    unsigned long long acc2[4][4];
    {
        const float4* bp = reinterpret_cast<const float4*>(b2 + c0);
        float4 v0 = bp[0], v1 = bp[1];
        unsigned long long p0 = pack2(v0.x, v0.y), p1 = pack2(v0.z, v0.w);
        unsigned long long p2 = pack2(v1.x, v1.y), p3 = pack2(v1.z, v1.w);
#pragma unroll
        for (int i = 0; i < 4; i++) {
            acc2[i][0] = p0; acc2[i][1] = p1; acc2[i][2] = p2; acc2[i][3] = p3;
        }
    }

    for (int k0 = 0; k0 < HID_; k0 += KB) {
        __syncthreads();
        {
            const float4* g =
                reinterpret_cast<const float4*>(W2 + (size_t)k0 * HID_);
            float4* dst = reinterpret_cast<float4*>(sW);
#pragma unroll
            for (int i = 0; i < 4; i++) dst[t + i * 256] = g[t + i * 256];
        }
        __syncthreads();
#pragma unroll
        for (int k = 0; k < KB; k++) {
            const ulonglong2* wr =
                reinterpret_cast<const ulonglong2*>(sW + k * HID_ + c0);
            ulonglong2 wA = wr[0], wB = wr[1];
#pragma unroll
            for (int i = 0; i < 4; i++) {
                float a = sH[(r0 + i) * HID_ + k0 + k];
                unsigned long long ap = pack2(a, a);
                ffma2(acc2[i][0], ap, wA.x);
                ffma2(acc2[i][1], ap, wA.y);
                ffma2(acc2[i][2], ap, wB.x);
                ffma2(acc2[i][3], ap, wB.y);
            }
        }
    }

    // ---------------- epilogue: relu + dot with W3, reduce ----------------
    float s[4] = {0.f, 0.f, 0.f, 0.f};
    {
        float w[8];
#pragma unroll
        for (int j = 0; j < 8; j++) w[j] = W3[c0 + j];
#pragma unroll
        for (int i = 0; i < 4; i++) {
#pragma unroll
            for (int jp = 0; jp < 4; jp++) {
                float2 v = unpack2(acc2[i][jp]);
                s[i] = fmaf(fmaxf(v.x, 0.f), w[2 * jp], s[i]);
                s[i] = fmaf(fmaxf(v.y, 0.f), w[2 * jp + 1], s[i]);
            }
        }
    }
    // warp reduce (rows are uniform within a warp)
#pragma unroll
    for (int i = 0; i < 4; i++) {
#pragma unroll
        for (int off = 16; off; off >>= 1)
            s[i] += __shfl_xor_sync(0xffffffffu, s[i], off);
    }
    __syncthreads();  // sW reads done before sRed reuse region written
    int lane = t & 31, wp = (t >> 5) & 1;
    if (lane == 0) {
#pragma unroll
        for (int i = 0; i < 4; i++) sRed[(r0 + i) * 2 + wp] = s[i];
    }
    __syncthreads();
    if (t < TILE_D) {
        float sc = sRed[t * 2] + sRed[t * 2 + 1] + b3[0];
        g_scores[b * NMAX_ + d0 + t] = sc;
    }
}

// ============================================================
// Kernel 3: masked log-softmax -> per-batch loss
// ============================================================
__global__ void loss_kernel(const int* __restrict__ ncnt,
                            const int* __restrict__ dests,
                            float* __restrict__ out) {
    __shared__ float red[256];
    int b = blockIdx.x, t = threadIdx.x;
    int lim = ncnt[b] - 1;  // valid: d < lim  (lim in [256,510])
    const float* sc = g_scores + b * NMAX_;
    float s1 = (t < lim) ? sc[t] : NEGV;
    int d2 = t + 256;
    float s2 = (d2 < lim) ? sc[d2] : NEGV;

    float m = fmaxf(s1, s2);
    red[t] = m;
    __syncthreads();
    for (int o = 128; o; o >>= 1) {
        if (t < o) red[t] = fmaxf(red[t], red[t + o]);
        __syncthreads();
    }
    float mx = red[0];
    __syncthreads();

    float e = expf(s1 - mx) + expf(s2 - mx);
    red[t] = e;
    __syncthreads();
    for (int o = 128; o; o >>= 1) {
        if (t < o) red[t] += red[t + o];
        __syncthreads();
    }
    if (t == 0) {
        float lse = mx + logf(red[0]);
        out[b] = lse - sc[dests[b]];  // loss = -(s_dest - lse)
    }
}

// ============================================================
extern "C" void kernel_launch(void* const* d_in, const int* in_sizes, int n_in,
                              void* d_out, int out_size) {
    const float* nodes = (const float*)d_in[0];
    const float* cc    = (const float*)d_in[1];
    const float* W1    = (const float*)d_in[2];
    const float* b1    = (const float*)d_in[3];
    const float* W2    = (const float*)d_in[4];
    const float* b2    = (const float*)d_in[5];
    const float* W3    = (const float*)d_in[6];
    const float* b3    = (const float*)d_in[7];
    const int* dirns   = (const int*)d_in[8];
    const int* ncnt    = (const int*)d_in[9];
    const int* dests   = (const int*)d_in[10];
    float* out = (float*)d_out;

    const int smem = (TILE_D * H_ + TILE_D * HID_ + KB * HID_ + TILE_D * 2) *
                     (int)sizeof(float);  // 65664 B
    cudaFuncSetAttribute(mlp_kernel,
                         cudaFuncAttributeMaxDynamicSharedMemorySize, smem);

    base_kernel<<<B_, 256>>>(nodes, cc, W1, b1, dirns, ncnt);
    dim3 grid(NMAX_ / TILE_D, B_);  // 32 x 256
    mlp_kernel<<<grid, 256, smem>>>(nodes, W1, W2, b2, W3, b3, dirns);
    loss_kernel<<<B_, 256>>>(ncnt, dests, out);
}

// round 6
// speedup vs baseline: 3.1327x; 3.1327x over previous
#include <cuda_runtime.h>
#include <cuda_bf16.h>
#include <cstdint>

// Problem constants
#define B_    256
#define NMAX_ 512
#define H_    256
#define C_    64
#define HID_  512
#define NEGV  (-1000000000.0f)

// GEMM tiling
#define CTA_M 128
#define CTA_N 256
#define KC    32
#define A_STRIDE 80                  // 32 bf16 = 64B + 16B pad
#define B_STRIDE 528                 // 256 bf16 = 512B + 16B pad
#define A_STAGE (CTA_M * A_STRIDE)   // 10240
#define B_STAGE (KC * B_STRIDE)      // 16896
#define STAGE   (A_STAGE + B_STAGE)  // 27136
#define SMEM_BYTES (2 * STAGE)       // 54272

// ---- device scratch (allocation-free rule) ----
__device__ float g_base[B_ * HID_];
__device__ float g_scores[B_ * NMAX_];
// split operands, K-extended layout [hi(K) | lo(K)] along last dim
__device__ __nv_bfloat16 g_nodes_s[(size_t)B_ * NMAX_ * (2 * H_)];   // 134MB
__device__ __nv_bfloat16 g_h1s[(size_t)B_ * NMAX_ * (2 * HID_)];     // 268MB
__device__ __nv_bfloat16 g_w1s[2][2 * H_][HID_];   // [variant][2K][N]
__device__ __nv_bfloat16 g_w2s[2 * HID_][HID_];    // [2K][N]

// ---- helpers ----
__device__ __forceinline__ uint32_t smem_u32(const void* p) {
    uint32_t a;
    asm("{ .reg .u64 t; cvta.to.shared.u64 t, %1; cvt.u32.u64 %0, t; }"
        : "=r"(a) : "l"(p));
    return a;
}
__device__ __forceinline__ void cp16(uint32_t s, const void* g) {
    asm volatile("cp.async.cg.shared.global [%0], [%1], 16;"
                 :: "r"(s), "l"(g) : "memory");
}
__device__ __forceinline__ void ldsm4(uint32_t addr, uint32_t* r) {
    asm volatile("ldmatrix.sync.aligned.m8n8.x4.shared.b16 {%0,%1,%2,%3}, [%4];"
                 : "=r"(r[0]), "=r"(r[1]), "=r"(r[2]), "=r"(r[3]) : "r"(addr));
}
__device__ __forceinline__ void ldsm4t(uint32_t addr, uint32_t* r) {
    asm volatile("ldmatrix.sync.aligned.m8n8.x4.trans.shared.b16 {%0,%1,%2,%3}, [%4];"
                 : "=r"(r[0]), "=r"(r[1]), "=r"(r[2]), "=r"(r[3]) : "r"(addr));
}
__device__ __forceinline__ void mma16816(float* c, const uint32_t* a,
                                         uint32_t b0, uint32_t b1) {
    asm volatile(
        "mma.sync.aligned.m16n8k16.row.col.f32.bf16.bf16.f32 "
        "{%0,%1,%2,%3}, {%4,%5,%6,%7}, {%8,%9}, {%0,%1,%2,%3};"
        : "+f"(c[0]), "+f"(c[1]), "+f"(c[2]), "+f"(c[3])
        : "r"(a[0]), "r"(a[1]), "r"(a[2]), "r"(a[3]), "r"(b0), "r"(b1));
}
// split two fp32 into packed bf16 hi-pair and lo-pair
__device__ __forceinline__ void split2(float x0, float x1,
                                       uint32_t& hi, uint32_t& lo) {
    __nv_bfloat16 h0 = __float2bfloat16(x0), h1 = __float2bfloat16(x1);
    float r0 = x0 - __bfloat162float(h0), r1 = x1 - __bfloat162float(h1);
    __nv_bfloat16 l0 = __float2bfloat16(r0), l1 = __float2bfloat16(r1);
    hi = (uint32_t)__bfloat16_as_ushort(h0) |
         ((uint32_t)__bfloat16_as_ushort(h1) << 16);
    lo = (uint32_t)__bfloat16_as_ushort(l0) |
         ((uint32_t)__bfloat16_as_ushort(l1) << 16);
}

// ============================================================
// prep kernels
// ============================================================
__global__ void zero_scores_kernel() {
    g_scores[blockIdx.x * 256 + threadIdx.x] = 0.f;
}

__global__ void base_kernel(const float* __restrict__ nodes,
                            const float* __restrict__ cc,
                            const float* __restrict__ W1,
                            const float* __restrict__ b1,
                            const int* __restrict__ dirns,
                            const int* __restrict__ ncnt) {
    __shared__ float sS[H_];
    __shared__ float sC[C_];
    int b = blockIdx.x, t = threadIdx.x;
    int nc = ncnt[b];
    const float* src = nodes + ((size_t)b * NMAX_ + (size_t)(nc - 1)) * H_;
    sS[t] = src[t];
    if (t < C_) sC[t] = cc[b * C_ + t];
    __syncthreads();
    int off_src = (dirns[b] == 1) ? H_ : 0;
    int j = t;
    float a0 = b1[j], a1 = b1[j + 256];
    const float* Wp = W1 + (size_t)off_src * HID_;
#pragma unroll 4
    for (int k = 0; k < H_; k++) {
        float s = sS[k];
        a0 = fmaf(s, Wp[(size_t)k * HID_ + j], a0);
        a1 = fmaf(s, Wp[(size_t)k * HID_ + j + 256], a1);
    }
    const float* Wc = W1 + (size_t)(2 * H_) * HID_;
#pragma unroll 4
    for (int k = 0; k < C_; k++) {
        float s = sC[k];
        a0 = fmaf(s, Wc[(size_t)k * HID_ + j], a0);
        a1 = fmaf(s, Wc[(size_t)k * HID_ + j + 256], a1);
    }
    g_base[b * HID_ + j] = a0;
    g_base[b * HID_ + j + 256] = a1;
}

__global__ void split_nodes_kernel(const float* __restrict__ nodes) {
    int row = blockIdx.x, b = blockIdx.y, t = threadIdx.x;  // 128 thr
    const float2* src =
        (const float2*)(nodes + ((size_t)b * NMAX_ + row) * H_);
    float2 v = src[t];
    uint32_t hi, lo;
    split2(v.x, v.y, hi, lo);
    uint32_t* dst =
        (uint32_t*)(g_nodes_s + ((size_t)b * NMAX_ + row) * (2 * H_));
    dst[t] = hi;
    dst[t + H_ / 2] = lo;
}

__global__ void w1s_kernel(const float* __restrict__ W1) {
    int r = blockIdx.x;   // 0..511 (hi rows then lo rows)
    int v = blockIdx.y;   // variant (cand offset 0 or H)
    int t = threadIdx.x;  // 0..255 -> cols 2t,2t+1
    int k = r & 255;
    const float2* src = (const float2*)(W1 + (size_t)(v * 256 + k) * HID_);
    float2 x = src[t];
    uint32_t hi, lo;
    split2(x.x, x.y, hi, lo);
    ((uint32_t*)g_w1s[v][r])[t] = (r < 256) ? hi : lo;
}

__global__ void w2s_kernel(const float* __restrict__ W2) {
    int r = blockIdx.x;   // 0..1023
    int t = threadIdx.x;  // 0..255
    int k = r & 511;
    const float2* src = (const float2*)(W2 + (size_t)k * HID_);
    float2 x = src[t];
    uint32_t hi, lo;
    split2(x.x, x.y, hi, lo);
    ((uint32_t*)g_w2s[r])[t] = (r < 512) ? hi : lo;
}

// ============================================================
// tensor-core GEMM (mma.sync bf16, split via K-extension)
// K_eff = 3K walked as [Ahi.Bhi | Ahi.Blo | Alo.Bhi]
// CTA: 128 rows x 256 cols; 16 warps (4M x 4N), warp tile 32x64
// ============================================================
template <int LAYER>
__global__ void __launch_bounds__(512) gemm_kernel(
    const int* __restrict__ dirns,
    const float* __restrict__ b2v,
    const float* __restrict__ W3v) {
    extern __shared__ char smdyn[];
    const uint32_t smb = smem_u32(smdyn);
    const int t = threadIdx.x;
    const int b = blockIdx.y;
    const int rt = blockIdx.x >> 1;
    const int nt = blockIdx.x & 1;
    const int d0 = rt * CTA_M, j0 = nt * CTA_N;

    constexpr int K = (LAYER == 1) ? 256 : 512;
    constexpr int K32 = K / 32;
    constexpr int NC = 3 * K32;

    const __nv_bfloat16* Asrc;
    const __nv_bfloat16* Bsrc;
    size_t Aw;
    if (LAYER == 1) {
        Asrc = g_nodes_s + ((size_t)b * NMAX_ + d0) * (2 * H_);
        Aw = 2 * H_;
        Bsrc = g_w1s[(dirns[b] == 1) ? 0 : 1][0];
    } else {
        Asrc = g_h1s + ((size_t)b * NMAX_ + d0) * (2 * HID_);
        Aw = 2 * HID_;
        Bsrc = g_w2s[0];
    }

    // term schedule: set0 = Ahi*Bhi, set1 = Ahi*Blo, set2 = Alo*Bhi
    auto kmapA = [&](int c) -> int {
        return (c < K32)     ? c * 32
             : (c < 2 * K32) ? (c - K32) * 32            // hi
                             : K + (c - 2 * K32) * 32;   // lo
    };
    auto kmapB = [&](int c) -> int {
        return (c < K32)     ? c * 32
             : (c < 2 * K32) ? K + (c - K32) * 32        // lo
                             : (c - 2 * K32) * 32;       // hi
    };
    auto load_chunk = [&](int c, int stage) {
        int cbA = kmapA(c);
        int cbB = kmapB(c);
        uint32_t sA = smb + stage * STAGE;
        uint32_t sB = sA + A_STAGE;
        {
            int row = t >> 2, q = t & 3;
            const char* g =
                (const char*)(Asrc + (size_t)row * Aw + cbA) + q * 16;
            cp16(sA + row * A_STRIDE + q * 16, g);
        }
#pragma unroll
        for (int j = 0; j < 2; j++) {
            int i = t + j * 512;
            int row = i >> 5, q = i & 31;
            const char* g =
                (const char*)(Bsrc + (size_t)(cbB + row) * HID_ + j0) + q * 16;
            cp16(sB + row * B_STRIDE + q * 16, g);
        }
        asm volatile("cp.async.commit_group;" ::: "memory");
    };

    load_chunk(0, 0);
    load_chunk(1, 1);

    const int l = t & 31, w = t >> 5, wm = w >> 2, wn = w & 3;
    const uint32_t aoff =
        (uint32_t)((wm * 32 + (l & 15)) * A_STRIDE + (l >> 4) * 16);
    const uint32_t boff =
        (uint32_t)((l & 15) * B_STRIDE + wn * 128 + (l >> 4) * 16);

    float cacc[2][8][4];
#pragma unroll
    for (int i = 0; i < 2; i++)
#pragma unroll
        for (int j = 0; j < 8; j++)
#pragma unroll
            for (int q = 0; q < 4; q++) cacc[i][j][q] = 0.f;

    for (int c = 0; c < NC; c++) {
        asm volatile("cp.async.wait_group 1;" ::: "memory");
        __syncthreads();
        int st = c & 1;
        uint32_t sA = smb + st * STAGE, sB = sA + A_STAGE;
        uint32_t a[2][2][4];
#pragma unroll
        for (int mi = 0; mi < 2; mi++)
#pragma unroll
            for (int kk = 0; kk < 2; kk++)
                ldsm4(sA + aoff + mi * 16 * A_STRIDE + kk * 32, a[mi][kk]);
#pragma unroll
        for (int ng = 0; ng < 4; ng++) {
            uint32_t b0[4], b1[4];
            ldsm4t(sB + boff + ng * 32, b0);
            ldsm4t(sB + boff + 16 * B_STRIDE + ng * 32, b1);
#pragma unroll
            for (int mi = 0; mi < 2; mi++) {
                mma16816(cacc[mi][2 * ng],     a[mi][0], b0[0], b0[1]);
                mma16816(cacc[mi][2 * ng + 1], a[mi][0], b0[2], b0[3]);
                mma16816(cacc[mi][2 * ng],     a[mi][1], b1[0], b1[1]);
                mma16816(cacc[mi][2 * ng + 1], a[mi][1], b1[2], b1[3]);
            }
        }
        __syncthreads();
        if (c + 2 < NC)
            load_chunk(c + 2, st);
        else
            asm volatile("cp.async.commit_group;" ::: "memory");
    }

    // ---------------- epilogue ----------------
    const int lrow = d0 + wm * 32 + (l >> 2);
    const int lcol0 = j0 + wn * 64 + (l & 3) * 2;
    if (LAYER == 1) {
#pragma unroll
        for (int mi = 0; mi < 2; mi++) {
            int r0 = lrow + mi * 16, r1 = r0 + 8;
#pragma unroll
            for (int nj = 0; nj < 8; nj++) {
                int col = lcol0 + nj * 8;
                float2 bs = *(const float2*)&g_base[b * HID_ + col];
                float x0 = fmaxf(cacc[mi][nj][0] + bs.x, 0.f);
                float x1 = fmaxf(cacc[mi][nj][1] + bs.y, 0.f);
                float x2 = fmaxf(cacc[mi][nj][2] + bs.x, 0.f);
                float x3 = fmaxf(cacc[mi][nj][3] + bs.y, 0.f);
                uint32_t hi, lo;
                split2(x0, x1, hi, lo);
                uint32_t* p0 = (uint32_t*)(g_h1s +
                    ((size_t)b * NMAX_ + r0) * (2 * HID_) + col);
                p0[0] = hi;
                p0[HID_ / 2] = lo;  // +512 bf16 elems
                split2(x2, x3, hi, lo);
                uint32_t* p1 = (uint32_t*)(g_h1s +
                    ((size_t)b * NMAX_ + r1) * (2 * HID_) + col);
                p1[0] = hi;
                p1[HID_ / 2] = lo;
            }
        }
    } else {
        float s[2][2] = {{0.f, 0.f}, {0.f, 0.f}};
#pragma unroll
        for (int mi = 0; mi < 2; mi++)
#pragma unroll
            for (int nj = 0; nj < 8; nj++) {
                int col = lcol0 + nj * 8;
                float2 bb = *(const float2*)&b2v[col];
                float2 ww = *(const float2*)&W3v[col];
                s[mi][0] += fmaxf(cacc[mi][nj][0] + bb.x, 0.f) * ww.x +
                            fmaxf(cacc[mi][nj][1] + bb.y, 0.f) * ww.y;
                s[mi][1] += fmaxf(cacc[mi][nj][2] + bb.x, 0.f) * ww.x +
                            fmaxf(cacc[mi][nj][3] + bb.y, 0.f) * ww.y;
            }
#pragma unroll
        for (int mi = 0; mi < 2; mi++)
#pragma unroll
            for (int h = 0; h < 2; h++) {
                float v = s[mi][h];
                v += __shfl_xor_sync(0xffffffffu, v, 1);
                v += __shfl_xor_sync(0xffffffffu, v, 2);
                if ((l & 3) == 0)
                    atomicAdd(&g_scores[b * NMAX_ + lrow + mi * 16 + h * 8], v);
            }
    }
}

// ============================================================
// loss: masked log-softmax -> per-batch loss (b3 cancels)
// ============================================================
__global__ void loss_kernel(const int* __restrict__ ncnt,
                            const int* __restrict__ dests,
                            float* __restrict__ out) {
    __shared__ float red[256];
    int b = blockIdx.x, t = threadIdx.x;
    int lim = ncnt[b] - 1;
    const float* sc = g_scores + b * NMAX_;
    float s1 = (t < lim) ? sc[t] : NEGV;
    int d2 = t + 256;
    float s2 = (d2 < lim) ? sc[d2] : NEGV;

    float m = fmaxf(s1, s2);
    red[t] = m;
    __syncthreads();
    for (int o = 128; o; o >>= 1) {
        if (t < o) red[t] = fmaxf(red[t], red[t + o]);
        __syncthreads();
    }
    float mx = red[0];
    __syncthreads();
    float e = expf(s1 - mx) + expf(s2 - mx);
    red[t] = e;
    __syncthreads();
    for (int o = 128; o; o >>= 1) {
        if (t < o) red[t] += red[t + o];
        __syncthreads();
    }
    if (t == 0) {
        float lse = mx + logf(red[0]);
        out[b] = lse - sc[dests[b]];
    }
}

// ============================================================
extern "C" void kernel_launch(void* const* d_in, const int* in_sizes, int n_in,
                              void* d_out, int out_size) {
    const float* nodes = (const float*)d_in[0];
    const float* cc    = (const float*)d_in[1];
    const float* W1    = (const float*)d_in[2];
    const float* b1    = (const float*)d_in[3];
    const float* W2    = (const float*)d_in[4];
    const float* b2    = (const float*)d_in[5];
    const float* W3    = (const float*)d_in[6];
    // d_in[7] = b3 (cancels in log_softmax)
    const int* dirns   = (const int*)d_in[8];
    const int* ncnt    = (const int*)d_in[9];
    const int* dests   = (const int*)d_in[10];
    float* out = (float*)d_out;

    cudaFuncSetAttribute(gemm_kernel<1>,
                         cudaFuncAttributeMaxDynamicSharedMemorySize, SMEM_BYTES);
    cudaFuncSetAttribute(gemm_kernel<2>,
                         cudaFuncAttributeMaxDynamicSharedMemorySize, SMEM_BYTES);

    zero_scores_kernel<<<512, 256>>>();
    base_kernel<<<B_, 256>>>(nodes, cc, W1, b1, dirns, ncnt);
    split_nodes_kernel<<<dim3(NMAX_, B_), 128>>>(nodes);
    w1s_kernel<<<dim3(512, 2), 256>>>(W1);
    w2s_kernel<<<1024, 256>>>(W2);

    dim3 grid(8, B_);
    gemm_kernel<1><<<grid, 512, SMEM_BYTES>>>(dirns, b2, W3);
    gemm_kernel<2><<<grid, 512, SMEM_BYTES>>>(dirns, b2, W3);
    loss_kernel<<<B_, 256>>>(ncnt, dests, out);
}

// round 7
// speedup vs baseline: 3.4171x; 1.0908x over previous
#include <cuda_runtime.h>
#include <cuda_bf16.h>
#include <cstdint>

// Problem constants
#define B_    256
#define NMAX_ 512
#define H_    256
#define C_    64
#define HID_  512
#define NEGV  (-1000000000.0f)

// GEMM tiling
#define CTA_M 128
#define CTA_N 256
#define KC    32
#define A_STRIDE 80                  // 32 bf16 = 64B + 16B pad
#define B_STRIDE 528                 // 256 bf16 = 512B + 16B pad
#define A_STAGE (CTA_M * A_STRIDE)   // 10240
#define B_STAGE (KC * B_STRIDE)      // 16896
#define STAGE   (A_STAGE + B_STAGE)  // 27136
#define NSTAGE  4
#define SMEM_BYTES (NSTAGE * STAGE)  // 108544

// ---- device scratch (allocation-free rule) ----
__device__ float g_base[B_ * HID_];
__device__ float g_scores[B_ * NMAX_];
// split operands, K-extended layout [hi(K) | lo(K)] along last dim
__device__ __nv_bfloat16 g_nodes_s[(size_t)B_ * NMAX_ * (2 * H_)];   // 134MB
__device__ __nv_bfloat16 g_h1s[(size_t)B_ * NMAX_ * (2 * HID_)];     // 268MB
__device__ __nv_bfloat16 g_w1s[2][2 * H_][HID_];   // [variant][2K][N]
__device__ __nv_bfloat16 g_w2s[2 * HID_][HID_];    // [2K][N]

// ---- helpers ----
__device__ __forceinline__ uint32_t smem_u32(const void* p) {
    uint32_t a;
    asm("{ .reg .u64 t; cvta.to.shared.u64 t, %1; cvt.u32.u64 %0, t; }"
        : "=r"(a) : "l"(p));
    return a;
}
__device__ __forceinline__ void cp16(uint32_t s, const void* g) {
    asm volatile("cp.async.cg.shared.global [%0], [%1], 16;"
                 :: "r"(s), "l"(g) : "memory");
}
__device__ __forceinline__ void ldsm4(uint32_t addr, uint32_t* r) {
    asm volatile("ldmatrix.sync.aligned.m8n8.x4.shared.b16 {%0,%1,%2,%3}, [%4];"
                 : "=r"(r[0]), "=r"(r[1]), "=r"(r[2]), "=r"(r[3]) : "r"(addr));
}
__device__ __forceinline__ void ldsm4t(uint32_t addr, uint32_t* r) {
    asm volatile("ldmatrix.sync.aligned.m8n8.x4.trans.shared.b16 {%0,%1,%2,%3}, [%4];"
                 : "=r"(r[0]), "=r"(r[1]), "=r"(r[2]), "=r"(r[3]) : "r"(addr));
}
__device__ __forceinline__ void mma16816(float* c, const uint32_t* a,
                                         uint32_t b0, uint32_t b1) {
    asm volatile(
        "mma.sync.aligned.m16n8k16.row.col.f32.bf16.bf16.f32 "
        "{%0,%1,%2,%3}, {%4,%5,%6,%7}, {%8,%9}, {%0,%1,%2,%3};"
        : "+f"(c[0]), "+f"(c[1]), "+f"(c[2]), "+f"(c[3])
        : "r"(a[0]), "r"(a[1]), "r"(a[2]), "r"(a[3]), "r"(b0), "r"(b1));
}
// split two fp32 into packed bf16 hi-pair and lo-pair
__device__ __forceinline__ void split2(float x0, float x1,
                                       uint32_t& hi, uint32_t& lo) {
    __nv_bfloat16 h0 = __float2bfloat16(x0), h1 = __float2bfloat16(x1);
    float r0 = x0 - __bfloat162float(h0), r1 = x1 - __bfloat162float(h1);
    __nv_bfloat16 l0 = __float2bfloat16(r0), l1 = __float2bfloat16(r1);
    hi = (uint32_t)__bfloat16_as_ushort(h0) |
         ((uint32_t)__bfloat16_as_ushort(h1) << 16);
    lo = (uint32_t)__bfloat16_as_ushort(l0) |
         ((uint32_t)__bfloat16_as_ushort(l1) << 16);
}

// ============================================================
// Fused prep kernel: block ranges do independent jobs concurrently.
//   [0,256)        base (per-batch layer-1 constant)
//   [256,2304)     split nodes -> g_nodes_s (grid-stride)
//   [2304,3328)    w1 split/transpose tiles
//   [3328,4352)    w2 split tiles
//   [4352,4864)    zero scores
// ============================================================
#define PREP_BLOCKS 4864
__global__ void __launch_bounds__(256) prep_kernel(
    const float* __restrict__ nodes,
    const float* __restrict__ cc,
    const float* __restrict__ W1,
    const float* __restrict__ b1,
    const float* __restrict__ W2,
    const int* __restrict__ dirns,
    const int* __restrict__ ncnt) {
    int blk = blockIdx.x;
    int t = threadIdx.x;
    if (blk < 256) {
        // ---- base ----
        __shared__ float sS[H_];
        __shared__ float sC[C_];
        int b = blk;
        int nc = ncnt[b];
        const float* src = nodes + ((size_t)b * NMAX_ + (size_t)(nc - 1)) * H_;
        sS[t] = src[t];
        if (t < C_) sC[t] = cc[b * C_ + t];
        __syncthreads();
        int off_src = (dirns[b] == 1) ? H_ : 0;
        int j = t;
        float a0 = b1[j], a1 = b1[j + 256];
        const float* Wp = W1 + (size_t)off_src * HID_;
#pragma unroll 8
        for (int k = 0; k < H_; k++) {
            float s = sS[k];
            a0 = fmaf(s, Wp[(size_t)k * HID_ + j], a0);
            a1 = fmaf(s, Wp[(size_t)k * HID_ + j + 256], a1);
        }
        const float* Wc = W1 + (size_t)(2 * H_) * HID_;
#pragma unroll 8
        for (int k = 0; k < C_; k++) {
            float s = sC[k];
            a0 = fmaf(s, Wc[(size_t)k * HID_ + j], a0);
            a1 = fmaf(s, Wc[(size_t)k * HID_ + j + 256], a1);
        }
        g_base[b * HID_ + j] = a0;
        g_base[b * HID_ + j + 256] = a1;
    } else if (blk < 2304) {
        // ---- split nodes: 16.7M float2 pairs, grid-stride ----
        const float2* src = (const float2*)nodes;
        uint32_t* dst = (uint32_t*)g_nodes_s;
        int idx = (blk - 256) * 256 + t;
        const int STRIDE = 2048 * 256;
        const int TOTAL = B_ * NMAX_ * (H_ / 2);  // 16777216
#pragma unroll 4
        for (int p = idx; p < TOTAL; p += STRIDE) {
            float2 v = src[p];
            uint32_t hi, lo;
            split2(v.x, v.y, hi, lo);
            int row = p >> 7, i = p & 127;
            dst[row * 256 + i] = hi;
            dst[row * 256 + 128 + i] = lo;
        }
    } else if (blk < 3328) {
        // ---- w1 split: u = (v, r) ----
        int u = blk - 2304;
        int v = u >> 9, r = u & 511;
        int k = r & 255;
        const float2* src = (const float2*)(W1 + (size_t)(v * 256 + k) * HID_);
        float2 x = src[t];
        uint32_t hi, lo;
        split2(x.x, x.y, hi, lo);
        ((uint32_t*)g_w1s[v][r])[t] = (r < 256) ? hi : lo;
    } else if (blk < 4352) {
        // ---- w2 split ----
        int r = blk - 3328;
        int k = r & 511;
        const float2* src = (const float2*)(W2 + (size_t)k * HID_);
        float2 x = src[t];
        uint32_t hi, lo;
        split2(x.x, x.y, hi, lo);
        ((uint32_t*)g_w2s[r])[t] = (r < 512) ? hi : lo;
    } else {
        // ---- zero scores ----
        int z = blk - 4352;
        g_scores[z * 256 + t] = 0.f;
    }
}

// ============================================================
// tensor-core GEMM (mma.sync bf16, split via K-extension)
// K_eff = 3K walked as [Ahi.Bhi | Ahi.Blo | Alo.Bhi]
// CTA: 128 rows x 256 cols; 16 warps (4M x 4N), warp tile 32x64
// 4-stage cp.async pipeline, one __syncthreads per chunk.
// ============================================================
template <int LAYER>
__global__ void __launch_bounds__(512) gemm_kernel(
    const int* __restrict__ dirns,
    const float* __restrict__ b2v,
    const float* __restrict__ W3v) {
    extern __shared__ char smdyn[];
    const uint32_t smb = smem_u32(smdyn);
    const int t = threadIdx.x;
    const int b = blockIdx.y;
    const int rt = blockIdx.x >> 1;
    const int nt = blockIdx.x & 1;
    const int d0 = rt * CTA_M, j0 = nt * CTA_N;

    constexpr int K = (LAYER == 1) ? 256 : 512;
    constexpr int K32 = K / 32;
    constexpr int NC = 3 * K32;

    const __nv_bfloat16* Asrc;
    const __nv_bfloat16* Bsrc;
    size_t Aw;
    if (LAYER == 1) {
        Asrc = g_nodes_s + ((size_t)b * NMAX_ + d0) * (2 * H_);
        Aw = 2 * H_;
        Bsrc = g_w1s[(dirns[b] == 1) ? 0 : 1][0];
    } else {
        Asrc = g_h1s + ((size_t)b * NMAX_ + d0) * (2 * HID_);
        Aw = 2 * HID_;
        Bsrc = g_w2s[0];
    }

    // term schedule: set0 = Ahi*Bhi, set1 = Ahi*Blo, set2 = Alo*Bhi
    auto kmapA = [&](int c) -> int {
        return (c < K32)     ? c * 32
             : (c < 2 * K32) ? (c - K32) * 32            // hi
                             : K + (c - 2 * K32) * 32;   // lo
    };
    auto kmapB = [&](int c) -> int {
        return (c < K32)     ? c * 32
             : (c < 2 * K32) ? K + (c - K32) * 32        // lo
                             : (c - 2 * K32) * 32;       // hi
    };
    auto load_chunk = [&](int c, int stage) {
        int cbA = kmapA(c);
        int cbB = kmapB(c);
        uint32_t sA = smb + stage * STAGE;
        uint32_t sB = sA + A_STAGE;
        {
            int row = t >> 2, q = t & 3;
            const char* g =
                (const char*)(Asrc + (size_t)row * Aw + cbA) + q * 16;
            cp16(sA + row * A_STRIDE + q * 16, g);
        }
#pragma unroll
        for (int j = 0; j < 2; j++) {
            int i = t + j * 512;
            int row = i >> 5, q = i & 31;
            const char* g =
                (const char*)(Bsrc + (size_t)(cbB + row) * HID_ + j0) + q * 16;
            cp16(sB + row * B_STRIDE + q * 16, g);
        }
        asm volatile("cp.async.commit_group;" ::: "memory");
    };

    load_chunk(0, 0);
    load_chunk(1, 1);
    load_chunk(2, 2);

    const int l = t & 31, w = t >> 5, wm = w >> 2, wn = w & 3;
    const uint32_t aoff =
        (uint32_t)((wm * 32 + (l & 15)) * A_STRIDE + (l >> 4) * 16);
    const uint32_t boff =
        (uint32_t)((l & 15) * B_STRIDE + wn * 128 + (l >> 4) * 16);

    float cacc[2][8][4];
#pragma unroll
    for (int i = 0; i < 2; i++)
#pragma unroll
        for (int j = 0; j < 8; j++)
#pragma unroll
            for (int q = 0; q < 4; q++) cacc[i][j][q] = 0.f;

    for (int c = 0; c < NC; c++) {
        asm volatile("cp.async.wait_group 2;" ::: "memory");
        __syncthreads();
        // prefetch chunk c+3 into the stage freed at iteration c-1
        if (c + 3 < NC)
            load_chunk(c + 3, (c + 3) & (NSTAGE - 1));
        else
            asm volatile("cp.async.commit_group;" ::: "memory");

        const int st = c & (NSTAGE - 1);
        const uint32_t sA = smb + st * STAGE, sB = sA + A_STAGE;
        uint32_t a[2][2][4];
#pragma unroll
        for (int mi = 0; mi < 2; mi++)
#pragma unroll
            for (int kk = 0; kk < 2; kk++)
                ldsm4(sA + aoff + mi * 16 * A_STRIDE + kk * 32, a[mi][kk]);
#pragma unroll
        for (int ng = 0; ng < 4; ng++) {
            uint32_t b0[4], b1[4];
            ldsm4t(sB + boff + ng * 32, b0);
            ldsm4t(sB + boff + 16 * B_STRIDE + ng * 32, b1);
#pragma unroll
            for (int mi = 0; mi < 2; mi++) {
                mma16816(cacc[mi][2 * ng],     a[mi][0], b0[0], b0[1]);
                mma16816(cacc[mi][2 * ng + 1], a[mi][0], b0[2], b0[3]);
                mma16816(cacc[mi][2 * ng],     a[mi][1], b1[0], b1[1]);
                mma16816(cacc[mi][2 * ng + 1], a[mi][1], b1[2], b1[3]);
            }
        }
    }

    // ---------------- epilogue ----------------
    const int lrow = d0 + wm * 32 + (l >> 2);
    const int lcol0 = j0 + wn * 64 + (l & 3) * 2;
    if (LAYER == 1) {
#pragma unroll
        for (int mi = 0; mi < 2; mi++) {
            int r0 = lrow + mi * 16, r1 = r0 + 8;
#pragma unroll
            for (int nj = 0; nj < 8; nj++) {
                int col = lcol0 + nj * 8;
                float2 bs = *(const float2*)&g_base[b * HID_ + col];
                float x0 = fmaxf(cacc[mi][nj][0] + bs.x, 0.f);
                float x1 = fmaxf(cacc[mi][nj][1] + bs.y, 0.f);
                float x2 = fmaxf(cacc[mi][nj][2] + bs.x, 0.f);
                float x3 = fmaxf(cacc[mi][nj][3] + bs.y, 0.f);
                uint32_t hi, lo;
                split2(x0, x1, hi, lo);
                uint32_t* p0 = (uint32_t*)(g_h1s +
                    ((size_t)b * NMAX_ + r0) * (2 * HID_) + col);
                p0[0] = hi;
                p0[HID_ / 2] = lo;  // +512 bf16 elems
                split2(x2, x3, hi, lo);
                uint32_t* p1 = (uint32_t*)(g_h1s +
                    ((size_t)b * NMAX_ + r1) * (2 * HID_) + col);
                p1[0] = hi;
                p1[HID_ / 2] = lo;
            }
        }
    } else {
        float s[2][2] = {{0.f, 0.f}, {0.f, 0.f}};
#pragma unroll
        for (int mi = 0; mi < 2; mi++)
#pragma unroll
            for (int nj = 0; nj < 8; nj++) {
                int col = lcol0 + nj * 8;
                float2 bb = *(const float2*)&b2v[col];
                float2 ww = *(const float2*)&W3v[col];
                s[mi][0] += fmaxf(cacc[mi][nj][0] + bb.x, 0.f) * ww.x +
                            fmaxf(cacc[mi][nj][1] + bb.y, 0.f) * ww.y;
                s[mi][1] += fmaxf(cacc[mi][nj][2] + bb.x, 0.f) * ww.x +
                            fmaxf(cacc[mi][nj][3] + bb.y, 0.f) * ww.y;
            }
#pragma unroll
        for (int mi = 0; mi < 2; mi++)
#pragma unroll
            for (int h = 0; h < 2; h++) {
                float v = s[mi][h];
                v += __shfl_xor_sync(0xffffffffu, v, 1);
                v += __shfl_xor_sync(0xffffffffu, v, 2);
                if ((l & 3) == 0)
                    atomicAdd(&g_scores[b * NMAX_ + lrow + mi * 16 + h * 8], v);
            }
    }
}

// ============================================================
// loss: masked log-softmax -> per-batch loss (b3 cancels)
// ============================================================
__global__ void loss_kernel(const int* __restrict__ ncnt,
                            const int* __restrict__ dests,
                            float* __restrict__ out) {
    __shared__ float red[256];
    int b = blockIdx.x, t = threadIdx.x;
    int lim = ncnt[b] - 1;
    const float* sc = g_scores + b * NMAX_;
    float s1 = (t < lim) ? sc[t] : NEGV;
    int d2 = t + 256;
    float s2 = (d2 < lim) ? sc[d2] : NEGV;

    float m = fmaxf(s1, s2);
    red[t] = m;
    __syncthreads();
    for (int o = 128; o; o >>= 1) {
        if (t < o) red[t] = fmaxf(red[t], red[t + o]);
        __syncthreads();
    }
    float mx = red[0];
    __syncthreads();
    float e = expf(s1 - mx) + expf(s2 - mx);
    red[t] = e;
    __syncthreads();
    for (int o = 128; o; o >>= 1) {
        if (t < o) red[t] += red[t + o];
        __syncthreads();
    }
    if (t == 0) {
        float lse = mx + logf(red[0]);
        out[b] = lse - sc[dests[b]];
    }
}

// ============================================================
extern "C" void kernel_launch(void* const* d_in, const int* in_sizes, int n_in,
                              void* d_out, int out_size) {
    const float* nodes = (const float*)d_in[0];
    const float* cc    = (const float*)d_in[1];
    const float* W1    = (const float*)d_in[2];
    const float* b1    = (const float*)d_in[3];
    const float* W2    = (const float*)d_in[4];
    const float* b2    = (const float*)d_in[5];
    const float* W3    = (const float*)d_in[6];
    // d_in[7] = b3 (cancels in log_softmax)
    const int* dirns   = (const int*)d_in[8];
    const int* ncnt    = (const int*)d_in[9];
    const int* dests   = (const int*)d_in[10];
    float* out = (float*)d_out;

    cudaFuncSetAttribute(gemm_kernel<1>,
                         cudaFuncAttributeMaxDynamicSharedMemorySize, SMEM_BYTES);
    cudaFuncSetAttribute(gemm_kernel<2>,
                         cudaFuncAttributeMaxDynamicSharedMemorySize, SMEM_BYTES);

    prep_kernel<<<PREP_BLOCKS, 256>>>(nodes, cc, W1, b1, W2, dirns, ncnt);

    dim3 grid(8, B_);
    gemm_kernel<1><<<grid, 512, SMEM_BYTES>>>(dirns, b2, W3);
    gemm_kernel<2><<<grid, 512, SMEM_BYTES>>>(dirns, b2, W3);
    loss_kernel<<<B_, 256>>>(ncnt, dests, out);
}

// round 10
// speedup vs baseline: 5.8684x; 1.7174x over previous
#include <cuda_runtime.h>
#include <cuda_bf16.h>
#include <cstdint>

// Problem constants
#define B_    256
#define NMAX_ 512
#define H_    256
#define C_    64
#define HID_  512
#define NEGV  (-1000000000.0f)

// GEMM tiling: CTA 128M x 256N, KC=32, tf32 m16n8k8
#define CTA_M 128
#define CTA_N 256
#define KC    32
#define ROWB  144                    // 32 fp32 = 128B + 16B pad
#define A_STAGE (CTA_M * ROWB)       // 18432
#define B_STAGE (CTA_N * ROWB)       // 36864
#define STAGE   (A_STAGE + B_STAGE)  // 55296
#define NSTAGE  3
#define SMEM_BYTES (NSTAGE * STAGE)  // 165888

// ---- device scratch (allocation-free rule) ----
__device__ float g_base[B_ * HID_];
__device__ float g_scores[B_ * NMAX_];
__device__ float g_h1[(size_t)B_ * NMAX_ * HID_];     // 268MB, tf32-rounded fp32
__device__ float g_w1t[2][HID_][H_];                  // [variant][n][k], tf32-rounded
__device__ float g_w2t[HID_][HID_];                   // [n][k], tf32-rounded

// ---- helpers ----
__device__ __forceinline__ uint32_t smem_u32(const void* p) {
    uint32_t a;
    asm("{ .reg .u64 t; cvta.to.shared.u64 t, %1; cvt.u32.u64 %0, t; }"
        : "=r"(a) : "l"(p));
    return a;
}
__device__ __forceinline__ void cp16(uint32_t s, const void* g) {
    asm volatile("cp.async.cg.shared.global [%0], [%1], 16;"
                 :: "r"(s), "l"(g) : "memory");
}
__device__ __forceinline__ void ldsm4(uint32_t addr, uint32_t* r) {
    asm volatile("ldmatrix.sync.aligned.m8n8.x4.shared.b16 {%0,%1,%2,%3}, [%4];"
                 : "=r"(r[0]), "=r"(r[1]), "=r"(r[2]), "=r"(r[3]) : "r"(addr));
}
__device__ __forceinline__ void mma_tf32(float* c, const uint32_t* a,
                                         uint32_t b0, uint32_t b1) {
    asm volatile(
        "mma.sync.aligned.m16n8k8.row.col.f32.tf32.tf32.f32 "
        "{%0,%1,%2,%3}, {%4,%5,%6,%7}, {%8,%9}, {%0,%1,%2,%3};"
        : "+f"(c[0]), "+f"(c[1]), "+f"(c[2]), "+f"(c[3])
        : "r"(a[0]), "r"(a[1]), "r"(a[2]), "r"(a[3]), "r"(b0), "r"(b1));
}
__device__ __forceinline__ float tf32r(float x) {
    uint32_t d;
    asm("cvt.rna.tf32.f32 %0, %1;" : "=r"(d) : "f"(x));
    return __uint_as_float(d);
}
__device__ __forceinline__ uint32_t tf32r_u(uint32_t x) {
    uint32_t d;
    asm("{ .reg .f32 f; mov.b32 f, %1; cvt.rna.tf32.f32 %0, f; }"
        : "=r"(d) : "r"(x));
    return d;
}

// ============================================================
// Fused prep kernel, block ranges:
//   [0,256)      base (per-batch layer-1 constant, fp32 exact)
//   [256,512)    W2 transpose+round: 16x16 tiles of 32x32
//   [512,768)    W1 transpose+round: 2 variants x 8x16 tiles
//   [768,1280)   zero scores
// ============================================================
#define PREP_BLOCKS 1280
__global__ void __launch_bounds__(256) prep_kernel(
    const float* __restrict__ nodes,
    const float* __restrict__ cc,
    const float* __restrict__ W1,
    const float* __restrict__ b1,
    const float* __restrict__ W2,
    const int* __restrict__ dirns,
    const int* __restrict__ ncnt) {
    int blk = blockIdx.x;
    int t = threadIdx.x;
    if (blk < 256) {
        __shared__ float sS[H_];
        __shared__ float sC[C_];
        int b = blk;
        int nc = ncnt[b];
        const float* src = nodes + ((size_t)b * NMAX_ + (size_t)(nc - 1)) * H_;
        sS[t] = src[t];
        if (t < C_) sC[t] = cc[b * C_ + t];
        __syncthreads();
        int off_src = (dirns[b] == 1) ? H_ : 0;
        int j = t;
        float a0 = b1[j], a1 = b1[j + 256];
        const float* Wp = W1 + (size_t)off_src * HID_;
#pragma unroll 8
        for (int k = 0; k < H_; k++) {
            float s = sS[k];
            a0 = fmaf(s, Wp[(size_t)k * HID_ + j], a0);
            a1 = fmaf(s, Wp[(size_t)k * HID_ + j + 256], a1);
        }
        const float* Wc = W1 + (size_t)(2 * H_) * HID_;
#pragma unroll 8
        for (int k = 0; k < C_; k++) {
            float s = sC[k];
            a0 = fmaf(s, Wc[(size_t)k * HID_ + j], a0);
            a1 = fmaf(s, Wc[(size_t)k * HID_ + j + 256], a1);
        }
        g_base[b * HID_ + j] = a0;
        g_base[b * HID_ + j + 256] = a1;
    } else if (blk < 512) {
        // W2 [k][n] -> g_w2t [n][k], rounded
        __shared__ float s[32][33];
        int u = blk - 256;
        int k0 = (u >> 4) * 32, n0 = (u & 15) * 32;
        int tx = t & 31, ty = t >> 5;
#pragma unroll
        for (int i = 0; i < 4; i++)
            s[ty + 8 * i][tx] = W2[(size_t)(k0 + ty + 8 * i) * HID_ + n0 + tx];
        __syncthreads();
#pragma unroll
        for (int i = 0; i < 4; i++)
            g_w2t[n0 + ty + 8 * i][k0 + tx] = tf32r(s[tx][ty + 8 * i]);
    } else if (blk < 768) {
        // W1 rows [v*256, v*256+256) [k][n] -> g_w1t[v] [n][k], rounded
        __shared__ float s[32][33];
        int u = blk - 512;
        int v = u >> 7;
        u &= 127;
        int k0 = (u >> 4) * 32, n0 = (u & 15) * 32;
        int tx = t & 31, ty = t >> 5;
#pragma unroll
        for (int i = 0; i < 4; i++)
            s[ty + 8 * i][tx] =
                W1[(size_t)(v * 256 + k0 + ty + 8 * i) * HID_ + n0 + tx];
        __syncthreads();
#pragma unroll
        for (int i = 0; i < 4; i++)
            g_w1t[v][n0 + ty + 8 * i][k0 + tx] = tf32r(s[tx][ty + 8 * i]);
    } else {
        int z = blk - 768;
        g_scores[z * 256 + t] = 0.f;
    }
}

// ============================================================
// tf32 tensor-core GEMM, single pass.
// LAYER=1: h1 = relu(nodes_cand @ W1c^T-tiles + base), K=256, CVTA (round A)
// LAYER=2: scores += relu(h1 @ W2t + b2) . W3,        K=512
// CTA 128x256, 512 thr, 16 warps 4Mx4N, warp tile 32x64.
// 3-stage cp.async pipeline, 1 barrier/chunk. ldmatrix-as-32bit fragments.
// ============================================================
template <int LAYER>
__global__ void __launch_bounds__(512) gemm_kernel(
    const float* __restrict__ nodes,
    const int* __restrict__ dirns,
    const float* __restrict__ b2v,
    const float* __restrict__ W3v) {
    extern __shared__ char smdyn[];
    const uint32_t smb = smem_u32(smdyn);
    const int t = threadIdx.x;
    const int b = blockIdx.y;
    const int rt = blockIdx.x >> 1;
    const int nt = blockIdx.x & 1;
    const int d0 = rt * CTA_M, j0 = nt * CTA_N;

    constexpr int K = (LAYER == 1) ? 256 : 512;
    constexpr int NC = K / KC;

    const float* Asrc;  // [row][K], K-contig
    const float* Bsrc;  // [n][K],  K-contig
    if (LAYER == 1) {
        Asrc = nodes + ((size_t)b * NMAX_ + d0) * H_;
        Bsrc = &g_w1t[(dirns[b] == 1) ? 0 : 1][j0][0];
    } else {
        Asrc = g_h1 + ((size_t)b * NMAX_ + d0) * HID_;
        Bsrc = &g_w2t[j0][0];
    }

    auto load_chunk = [&](int c, int stage) {
        uint32_t sA = smb + stage * STAGE;
        uint32_t sB = sA + A_STAGE;
#pragma unroll
        for (int j = 0; j < 2; j++) {  // A: 128 rows x 128B
            int i = t + j * 512;
            int row = i >> 3, q = i & 7;
            const char* g = (const char*)(Asrc + (size_t)row * K + c * KC) + q * 16;
            cp16(sA + row * ROWB + q * 16, g);
        }
#pragma unroll
        for (int j = 0; j < 4; j++) {  // B: 256 rows x 128B
            int i = t + j * 512;
            int row = i >> 3, q = i & 7;
            const char* g = (const char*)(Bsrc + (size_t)row * K + c * KC) + q * 16;
            cp16(sB + row * ROWB + q * 16, g);
        }
        asm volatile("cp.async.commit_group;" ::: "memory");
    };

    load_chunk(0, 0);
    load_chunk(1, 1);

    const int l = t & 31, w = t >> 5, wm = w >> 2, wn = w & 3;
    // ldmatrix lane-address components (4 8x8(b16-view) mats = 8rows x 8 fp32)
    const int lrowsel = (l & 7) + ((l >> 3) & 1) * 8;  // row within 16
    const int lcolsel = (l >> 4) * 16;                 // byte offset: fp32 cols 4-7
    const uint32_t a_lane =
        (uint32_t)((wm * 32 + lrowsel) * ROWB + lcolsel);
    const int nrowsel = (l & 7) + (l >> 4) * 8;        // n within 16
    const int ncolsel = ((l >> 3) & 1) * 16;           // k cols 4-7
    const uint32_t b_lane =
        (uint32_t)((wn * 64 + nrowsel) * ROWB + ncolsel);

    float cacc[2][8][4];
#pragma unroll
    for (int i = 0; i < 2; i++)
#pragma unroll
        for (int j = 0; j < 8; j++)
#pragma unroll
            for (int q = 0; q < 4; q++) cacc[i][j][q] = 0.f;

    for (int c = 0; c < NC; c++) {
        asm volatile("cp.async.wait_group 1;" ::: "memory");
        __syncthreads();
        if (c + 2 < NC)
            load_chunk(c + 2, (c + 2) % NSTAGE);
        else
            asm volatile("cp.async.commit_group;" ::: "memory");

        const int st = c % NSTAGE;
        const uint32_t sA = smb + st * STAGE, sB = sA + A_STAGE;
#pragma unroll
        for (int ks = 0; ks < 4; ks++) {
            uint32_t a[2][4];
#pragma unroll
            for (int mi = 0; mi < 2; mi++) {
                ldsm4(sA + a_lane + mi * 16 * ROWB + ks * 32, a[mi]);
                if (LAYER == 1) {
#pragma unroll
                    for (int q = 0; q < 4; q++) a[mi][q] = tf32r_u(a[mi][q]);
                }
            }
#pragma unroll
            for (int nbp = 0; nbp < 4; nbp++) {
                uint32_t bq[4];  // r0=b0(nb), r1=b1(nb), r2=b0(nb+1), r3=b1(nb+1)
                ldsm4(sB + b_lane + nbp * 16 * ROWB + ks * 32, bq);
#pragma unroll
                for (int mi = 0; mi < 2; mi++) {
                    mma_tf32(cacc[mi][nbp * 2],     a[mi], bq[0], bq[1]);
                    mma_tf32(cacc[mi][nbp * 2 + 1], a[mi], bq[2], bq[3]);
                }
            }
        }
    }

    // ---------------- epilogue ----------------
    const int lrow = d0 + wm * 32 + (l >> 2);
    const int lcol0 = j0 + wn * 64 + (l & 3) * 2;
    if (LAYER == 1) {
#pragma unroll
        for (int mi = 0; mi < 2; mi++) {
            int r0 = lrow + mi * 16, r1 = r0 + 8;
#pragma unroll
            for (int nj = 0; nj < 8; nj++) {
                int col = lcol0 + nj * 8;
                float2 bs = *(const float2*)&g_base[b * HID_ + col];
                float2 v0, v1;
                v0.x = tf32r(fmaxf(cacc[mi][nj][0] + bs.x, 0.f));
                v0.y = tf32r(fmaxf(cacc[mi][nj][1] + bs.y, 0.f));
                v1.x = tf32r(fmaxf(cacc[mi][nj][2] + bs.x, 0.f));
                v1.y = tf32r(fmaxf(cacc[mi][nj][3] + bs.y, 0.f));
                *(float2*)&g_h1[((size_t)b * NMAX_ + r0) * HID_ + col] = v0;
                *(float2*)&g_h1[((size_t)b * NMAX_ + r1) * HID_ + col] = v1;
            }
        }
    } else {
        float s[2][2] = {{0.f, 0.f}, {0.f, 0.f}};
#pragma unroll
        for (int mi = 0; mi < 2; mi++)
#pragma unroll
            for (int nj = 0; nj < 8; nj++) {
                int col = lcol0 + nj * 8;
                float2 bb = *(const float2*)&b2v[col];
                float2 ww = *(const float2*)&W3v[col];
                s[mi][0] += fmaxf(cacc[mi][nj][0] + bb.x, 0.f) * ww.x +
                            fmaxf(cacc[mi][nj][1] + bb.y, 0.f) * ww.y;
                s[mi][1] += fmaxf(cacc[mi][nj][2] + bb.x, 0.f) * ww.x +
                            fmaxf(cacc[mi][nj][3] + bb.y, 0.f) * ww.y;
            }
#pragma unroll
        for (int mi = 0; mi < 2; mi++)
#pragma unroll
            for (int h = 0; h < 2; h++) {
                float v = s[mi][h];
                v += __shfl_xor_sync(0xffffffffu, v, 1);
                v += __shfl_xor_sync(0xffffffffu, v, 2);
                if ((l & 3) == 0)
                    atomicAdd(&g_scores[b * NMAX_ + lrow + mi * 16 + h * 8], v);
            }
    }
}

// ============================================================
// loss: masked log-softmax -> per-batch loss (b3 cancels)
// ============================================================
__global__ void loss_kernel(const int* __restrict__ ncnt,
                            const int* __restrict__ dests,
                            float* __restrict__ out) {
    __shared__ float red[256];
    int b = blockIdx.x, t = threadIdx.x;
    int lim = ncnt[b] - 1;
    const float* sc = g_scores + b * NMAX_;
    float s1 = (t < lim) ? sc[t] : NEGV;
    int d2 = t + 256;
    float s2 = (d2 < lim) ? sc[d2] : NEGV;

    float m = fmaxf(s1, s2);
    red[t] = m;
    __syncthreads();
    for (int o = 128; o; o >>= 1) {
        if (t < o) red[t] = fmaxf(red[t], red[t + o]);
        __syncthreads();
    }
    float mx = red[0];
    __syncthreads();
    float e = expf(s1 - mx) + expf(s2 - mx);
    red[t] = e;
    __syncthreads();
    for (int o = 128; o; o >>= 1) {
        if (t < o) red[t] += red[t + o];
        __syncthreads();
    }
    if (t == 0) {
        float lse = mx + logf(red[0]);
        out[b] = lse - sc[dests[b]];
    }
}

// ============================================================
extern "C" void kernel_launch(void* const* d_in, const int* in_sizes, int n_in,
                              void* d_out, int out_size) {
    const float* nodes = (const float*)d_in[0];
    const float* cc    = (const float*)d_in[1];
    const float* W1    = (const float*)d_in[2];
    const float* b1    = (const float*)d_in[3];
    const float* W2    = (const float*)d_in[4];
    const float* b2    = (const float*)d_in[5];
    const float* W3    = (const float*)d_in[6];
    // d_in[7] = b3 (cancels in log_softmax)
    const int* dirns   = (const int*)d_in[8];
    const int* ncnt    = (const int*)d_in[9];
    const int* dests   = (const int*)d_in[10];
    float* out = (float*)d_out;

    cudaFuncSetAttribute(gemm_kernel<1>,
                         cudaFuncAttributeMaxDynamicSharedMemorySize, SMEM_BYTES);
    cudaFuncSetAttribute(gemm_kernel<2>,
                         cudaFuncAttributeMaxDynamicSharedMemorySize, SMEM_BYTES);

    prep_kernel<<<PREP_BLOCKS, 256>>>(nodes, cc, W1, b1, W2, dirns, ncnt);

    dim3 grid(8, B_);
    gemm_kernel<1><<<grid, 512, SMEM_BYTES>>>(nodes, dirns, b2, W3);
    gemm_kernel<2><<<grid, 512, SMEM_BYTES>>>(nodes, dirns, b2, W3);
    loss_kernel<<<B_, 256>>>(ncnt, dests, out);
}

// round 11
// speedup vs baseline: 8.8804x; 1.5133x over previous
#include <cuda_runtime.h>
#include <cuda_bf16.h>
#include <cstdint>

// Problem constants
#define B_    256
#define NMAX_ 512
#define H_    256
#define C_    64
#define HID_  512
#define NEGV  (-1000000000.0f)

// GEMM tiling: CTA 128M x 256N, KC=64 bf16, mma m16n8k16
#define CTA_M 128
#define CTA_N 256
#define KC    64
#define ROWB  144                    // 64 bf16 = 128B + 16B pad
#define A_STAGE (CTA_M * ROWB)       // 18432
#define B_STAGE (CTA_N * ROWB)       // 36864
#define STAGE   (A_STAGE + B_STAGE)  // 55296
#define NSTAGE  3
#define SMEM_BYTES (NSTAGE * STAGE)  // 165888

// ---- device scratch (allocation-free rule) ----
__device__ float g_base[B_ * HID_];
__device__ float g_scores[B_ * NMAX_];
__device__ __nv_bfloat16 g_nodes_b[(size_t)B_ * NMAX_ * H_];    // 67MB
__device__ __nv_bfloat16 g_h1b[(size_t)B_ * NMAX_ * HID_];      // 134MB
__device__ __nv_bfloat16 g_w1b[2][HID_][H_];   // [variant][n][k]
__device__ __nv_bfloat16 g_w2b[HID_][HID_];    // [n][k]

// ---- helpers ----
__device__ __forceinline__ uint32_t smem_u32(const void* p) {
    uint32_t a;
    asm("{ .reg .u64 t; cvta.to.shared.u64 t, %1; cvt.u32.u64 %0, t; }"
        : "=r"(a) : "l"(p));
    return a;
}
__device__ __forceinline__ void cp16(uint32_t s, const void* g) {
    asm volatile("cp.async.cg.shared.global [%0], [%1], 16;"
                 :: "r"(s), "l"(g) : "memory");
}
__device__ __forceinline__ void ldsm4(uint32_t addr, uint32_t* r) {
    asm volatile("ldmatrix.sync.aligned.m8n8.x4.shared.b16 {%0,%1,%2,%3}, [%4];"
                 : "=r"(r[0]), "=r"(r[1]), "=r"(r[2]), "=r"(r[3]) : "r"(addr));
}
__device__ __forceinline__ void mma16816(float* c, const uint32_t* a,
                                         uint32_t b0, uint32_t b1) {
    asm volatile(
        "mma.sync.aligned.m16n8k16.row.col.f32.bf16.bf16.f32 "
        "{%0,%1,%2,%3}, {%4,%5,%6,%7}, {%8,%9}, {%0,%1,%2,%3};"
        : "+f"(c[0]), "+f"(c[1]), "+f"(c[2]), "+f"(c[3])
        : "r"(a[0]), "r"(a[1]), "r"(a[2]), "r"(a[3]), "r"(b0), "r"(b1));
}
__device__ __forceinline__ uint32_t packbf(float lo, float hi) {
    __nv_bfloat162 v = __floats2bfloat162_rn(lo, hi);  // .x=lo(low half)
    return *(uint32_t*)&v;
}

// ============================================================
// Fused prep kernel, block ranges:
//   [0,256)       base (per-batch layer-1 constant, fp32 exact)
//   [256,2304)    nodes fp32 -> bf16 (grid-stride over 16.7M float2)
//   [2304,2560)   W1 transpose+convert: 2 variants x 128 32x32 tiles
//   [2560,2816)   W2 transpose+convert: 256 32x32 tiles
//   [2816,3328)   zero scores
// ============================================================
#define PREP_BLOCKS 3328
__global__ void __launch_bounds__(256) prep_kernel(
    const float* __restrict__ nodes,
    const float* __restrict__ cc,
    const float* __restrict__ W1,
    const float* __restrict__ b1,
    const float* __restrict__ W2,
    const int* __restrict__ dirns,
    const int* __restrict__ ncnt) {
    int blk = blockIdx.x;
    int t = threadIdx.x;
    if (blk < 256) {
        __shared__ float sS[H_];
        __shared__ float sC[C_];
        int b = blk;
        int nc = ncnt[b];
        const float* src = nodes + ((size_t)b * NMAX_ + (size_t)(nc - 1)) * H_;
        sS[t] = src[t];
        if (t < C_) sC[t] = cc[b * C_ + t];
        __syncthreads();
        int off_src = (dirns[b] == 1) ? H_ : 0;
        int j = t;
        float a0 = b1[j], a1 = b1[j + 256];
        const float* Wp = W1 + (size_t)off_src * HID_;
#pragma unroll 8
        for (int k = 0; k < H_; k++) {
            float s = sS[k];
            a0 = fmaf(s, Wp[(size_t)k * HID_ + j], a0);
            a1 = fmaf(s, Wp[(size_t)k * HID_ + j + 256], a1);
        }
        const float* Wc = W1 + (size_t)(2 * H_) * HID_;
#pragma unroll 8
        for (int k = 0; k < C_; k++) {
            float s = sC[k];
            a0 = fmaf(s, Wc[(size_t)k * HID_ + j], a0);
            a1 = fmaf(s, Wc[(size_t)k * HID_ + j + 256], a1);
        }
        g_base[b * HID_ + j] = a0;
        g_base[b * HID_ + j + 256] = a1;
    } else if (blk < 2304) {
        // nodes fp32 -> bf16, flat
        const float2* src = (const float2*)nodes;
        uint32_t* dst = (uint32_t*)g_nodes_b;
        int idx = (blk - 256) * 256 + t;
        const int STRIDE = 2048 * 256;
        const int TOTAL = B_ * NMAX_ * (H_ / 2);  // 16777216
#pragma unroll 4
        for (int p = idx; p < TOTAL; p += STRIDE) {
            float2 v = src[p];
            dst[p] = packbf(v.x, v.y);
        }
    } else if (blk < 2560) {
        // W1 slice [256k][512n] -> g_w1b[v][n][k] bf16, 32x32 tiles
        __shared__ float s[32][33];
        int u = blk - 2304;
        int v = u >> 7;
        u &= 127;                       // 8 k-tiles x 16 n-tiles
        int k0 = (u >> 4) * 32, n0 = (u & 15) * 32;
        int tx = t & 31, ty = t >> 5;
#pragma unroll
        for (int i = 0; i < 4; i++)
            s[ty + 8 * i][tx] =
                W1[(size_t)(v * 256 + k0 + ty + 8 * i) * HID_ + n0 + tx];
        __syncthreads();
        // write 32 n-rows x 16 k-pairs
        int n = t & 31, kp0 = t >> 5;   // kp0 in 0..7
#pragma unroll
        for (int i = 0; i < 2; i++) {
            int kp = kp0 + 8 * i;
            uint32_t w = packbf(s[2 * kp][n], s[2 * kp + 1][n]);
            ((uint32_t*)&g_w1b[v][n0 + n][0])[(k0 >> 1) + kp] = w;
        }
    } else if (blk < 2816) {
        // W2 [512k][512n] -> g_w2b[n][k] bf16, 32x32 tiles (16x16 grid)
        __shared__ float s[32][33];
        int u = blk - 2560;
        int k0 = (u >> 4) * 32, n0 = (u & 15) * 32;
        int tx = t & 31, ty = t >> 5;
#pragma unroll
        for (int i = 0; i < 4; i++)
            s[ty + 8 * i][tx] = W2[(size_t)(k0 + ty + 8 * i) * HID_ + n0 + tx];
        __syncthreads();
        int n = t & 31, kp0 = t >> 5;
#pragma unroll
        for (int i = 0; i < 2; i++) {
            int kp = kp0 + 8 * i;
            uint32_t w = packbf(s[2 * kp][n], s[2 * kp + 1][n]);
            ((uint32_t*)&g_w2b[n0 + n][0])[(k0 >> 1) + kp] = w;
        }
    } else {
        int z = blk - 2816;
        g_scores[z * 256 + t] = 0.f;
    }
}

// ============================================================
// bf16 tensor-core GEMM, single pass.
// LAYER=1: h1 = relu(nodes_b @ W1b[n][k] + base), K=256 -> g_h1b (bf16)
// LAYER=2: scores += relu(h1b @ W2b + b2) . W3,   K=512
// CTA 128x256, 512 thr, 16 warps 4Mx4N, warp tile 32x64.
// 3-stage cp.async pipeline, 1 barrier/chunk.
// A and B both loaded with non-trans ldmatrix ([m][k] and [n][k] layouts).
// ============================================================
template <int LAYER>
__global__ void __launch_bounds__(512) gemm_kernel(
    const int* __restrict__ dirns,
    const float* __restrict__ b2v,
    const float* __restrict__ W3v) {
    extern __shared__ char smdyn[];
    const uint32_t smb = smem_u32(smdyn);
    const int t = threadIdx.x;
    const int b = blockIdx.y;
    const int rt = blockIdx.x >> 1;
    const int nt = blockIdx.x & 1;
    const int d0 = rt * CTA_M, j0 = nt * CTA_N;

    constexpr int K = (LAYER == 1) ? 256 : 512;
    constexpr int NC = K / KC;

    const __nv_bfloat16* Asrc;  // [row][K]
    const __nv_bfloat16* Bsrc;  // [n][K]
    if (LAYER == 1) {
        Asrc = g_nodes_b + ((size_t)b * NMAX_ + d0) * H_;
        Bsrc = &g_w1b[(dirns[b] == 1) ? 0 : 1][j0][0];
    } else {
        Asrc = g_h1b + ((size_t)b * NMAX_ + d0) * HID_;
        Bsrc = &g_w2b[j0][0];
    }

    auto load_chunk = [&](int c, int stage) {
        uint32_t sA = smb + stage * STAGE;
        uint32_t sB = sA + A_STAGE;
#pragma unroll
        for (int j = 0; j < 2; j++) {  // A: 128 rows x 128B
            int i = t + j * 512;
            int row = i >> 3, q = i & 7;
            const char* g = (const char*)(Asrc + (size_t)row * K + c * KC) + q * 16;
            cp16(sA + row * ROWB + q * 16, g);
        }
#pragma unroll
        for (int j = 0; j < 4; j++) {  // B: 256 rows x 128B
            int i = t + j * 512;
            int row = i >> 3, q = i & 7;
            const char* g = (const char*)(Bsrc + (size_t)row * K + c * KC) + q * 16;
            cp16(sB + row * ROWB + q * 16, g);
        }
        asm volatile("cp.async.commit_group;" ::: "memory");
    };

    load_chunk(0, 0);
    load_chunk(1, 1);

    const int l = t & 31, w = t >> 5, wm = w >> 2, wn = w & 3;
    // ldmatrix lane addresses: 16 rows x 2 halves of 16B (k0-7 / k8-15)
    const uint32_t a_lane =
        (uint32_t)((wm * 32 + (l & 15)) * ROWB + (l >> 4) * 16);
    const uint32_t b_lane =
        (uint32_t)((wn * 64 + (l & 15)) * ROWB + (l >> 4) * 16);

    float cacc[2][8][4];
#pragma unroll
    for (int i = 0; i < 2; i++)
#pragma unroll
        for (int j = 0; j < 8; j++)
#pragma unroll
            for (int q = 0; q < 4; q++) cacc[i][j][q] = 0.f;

    for (int c = 0; c < NC; c++) {
        asm volatile("cp.async.wait_group 1;" ::: "memory");
        __syncthreads();
        if (c + 2 < NC)
            load_chunk(c + 2, (c + 2) % NSTAGE);
        else
            asm volatile("cp.async.commit_group;" ::: "memory");

        const int st = c % NSTAGE;
        const uint32_t sA = smb + st * STAGE, sB = sA + A_STAGE;
#pragma unroll
        for (int ks = 0; ks < 4; ks++) {  // 16 k per step
            uint32_t a[2][4];
#pragma unroll
            for (int mi = 0; mi < 2; mi++)
                ldsm4(sA + a_lane + mi * 16 * ROWB + ks * 32, a[mi]);
#pragma unroll
            for (int nbp = 0; nbp < 4; nbp++) {
                // non-trans ldsm on [n][k]: r0=b0(n0-7) r1=b0(n8-15)
                //                           r2=b1(n0-7) r3=b1(n8-15)
                uint32_t bq[4];
                ldsm4(sB + b_lane + nbp * 16 * ROWB + ks * 32, bq);
#pragma unroll
                for (int mi = 0; mi < 2; mi++) {
                    mma16816(cacc[mi][nbp * 2],     a[mi], bq[0], bq[2]);
                    mma16816(cacc[mi][nbp * 2 + 1], a[mi], bq[1], bq[3]);
                }
            }
        }
    }

    // ---------------- epilogue ----------------
    const int lrow = d0 + wm * 32 + (l >> 2);
    const int lcol0 = j0 + wn * 64 + (l & 3) * 2;
    if (LAYER == 1) {
#pragma unroll
        for (int mi = 0; mi < 2; mi++) {
            int r0 = lrow + mi * 16, r1 = r0 + 8;
#pragma unroll
            for (int nj = 0; nj < 8; nj++) {
                int col = lcol0 + nj * 8;
                float2 bs = *(const float2*)&g_base[b * HID_ + col];
                uint32_t v0 = packbf(fmaxf(cacc[mi][nj][0] + bs.x, 0.f),
                                     fmaxf(cacc[mi][nj][1] + bs.y, 0.f));
                uint32_t v1 = packbf(fmaxf(cacc[mi][nj][2] + bs.x, 0.f),
                                     fmaxf(cacc[mi][nj][3] + bs.y, 0.f));
                ((uint32_t*)g_h1b)[(((size_t)b * NMAX_ + r0) * HID_ + col) >> 1] = v0;
                ((uint32_t*)g_h1b)[(((size_t)b * NMAX_ + r1) * HID_ + col) >> 1] = v1;
            }
        }
    } else {
        float s[2][2] = {{0.f, 0.f}, {0.f, 0.f}};
#pragma unroll
        for (int mi = 0; mi < 2; mi++)
#pragma unroll
            for (int nj = 0; nj < 8; nj++) {
                int col = lcol0 + nj * 8;
                float2 bb = *(const float2*)&b2v[col];
                float2 ww = *(const float2*)&W3v[col];
                s[mi][0] += fmaxf(cacc[mi][nj][0] + bb.x, 0.f) * ww.x +
                            fmaxf(cacc[mi][nj][1] + bb.y, 0.f) * ww.y;
                s[mi][1] += fmaxf(cacc[mi][nj][2] + bb.x, 0.f) * ww.x +
                            fmaxf(cacc[mi][nj][3] + bb.y, 0.f) * ww.y;
            }
#pragma unroll
        for (int mi = 0; mi < 2; mi++)
#pragma unroll
            for (int h = 0; h < 2; h++) {
                float v = s[mi][h];
                v += __shfl_xor_sync(0xffffffffu, v, 1);
                v += __shfl_xor_sync(0xffffffffu, v, 2);
                if ((l & 3) == 0)
                    atomicAdd(&g_scores[b * NMAX_ + lrow + mi * 16 + h * 8], v);
            }
    }
}

// ============================================================
// loss: masked log-softmax -> per-batch loss (b3 cancels)
// ============================================================
__global__ void loss_kernel(const int* __restrict__ ncnt,
                            const int* __restrict__ dests,
                            float* __restrict__ out) {
    __shared__ float red[256];
    int b = blockIdx.x, t = threadIdx.x;
    int lim = ncnt[b] - 1;
    const float* sc = g_scores + b * NMAX_;
    float s1 = (t < lim) ? sc[t] : NEGV;
    int d2 = t + 256;
    float s2 = (d2 < lim) ? sc[d2] : NEGV;

    float m = fmaxf(s1, s2);
    red[t] = m;
    __syncthreads();
    for (int o = 128; o; o >>= 1) {
        if (t < o) red[t] = fmaxf(red[t], red[t + o]);
        __syncthreads();
    }
    float mx = red[0];
    __syncthreads();
    float e = expf(s1 - mx) + expf(s2 - mx);
    red[t] = e;
    __syncthreads();
    for (int o = 128; o; o >>= 1) {
        if (t < o) red[t] += red[t + o];
        __syncthreads();
    }
    if (t == 0) {
        float lse = mx + logf(red[0]);
        out[b] = lse - sc[dests[b]];
    }
}

// ============================================================
extern "C" void kernel_launch(void* const* d_in, const int* in_sizes, int n_in,
                              void* d_out, int out_size) {
    const float* nodes = (const float*)d_in[0];
    const float* cc    = (const float*)d_in[1];
    const float* W1    = (const float*)d_in[2];
    const float* b1    = (const float*)d_in[3];
    const float* W2    = (const float*)d_in[4];
    const float* b2    = (const float*)d_in[5];
    const float* W3    = (const float*)d_in[6];
    // d_in[7] = b3 (cancels in log_softmax)
    const int* dirns   = (const int*)d_in[8];
    const int* ncnt    = (const int*)d_in[9];
    const int* dests   = (const int*)d_in[10];
    float* out = (float*)d_out;

    cudaFuncSetAttribute(gemm_kernel<1>,
                         cudaFuncAttributeMaxDynamicSharedMemorySize, SMEM_BYTES);
    cudaFuncSetAttribute(gemm_kernel<2>,
                         cudaFuncAttributeMaxDynamicSharedMemorySize, SMEM_BYTES);

    prep_kernel<<<PREP_BLOCKS, 256>>>(nodes, cc, W1, b1, W2, dirns, ncnt);

    dim3 grid(8, B_);
    gemm_kernel<1><<<grid, 512, SMEM_BYTES>>>(dirns, b2, W3);
    gemm_kernel<2><<<grid, 512, SMEM_BYTES>>>(dirns, b2, W3);
    loss_kernel<<<B_, 256>>>(ncnt, dests, out);
}

// round 12
// speedup vs baseline: 10.2836x; 1.1580x over previous
#include <cuda_runtime.h>
#include <cuda_bf16.h>
#include <cstdint>

// Problem constants
#define B_    256
#define NMAX_ 512
#define H_    256
#define C_    64
#define HID_  512
#define NEGV  (-1000000000.0f)

// GEMM tiling: CTA 128M x 256N, KC=64 bf16, mma m16n8k16
#define CTA_M 128
#define CTA_N 256
#define KC    64
#define ROWB  144                    // 64 bf16 = 128B + 16B pad
#define A_STAGE (CTA_M * ROWB)       // 18432
#define B_STAGE (CTA_N * ROWB)       // 36864
#define STAGE   (A_STAGE + B_STAGE)  // 55296
#define NSTAGE  3
#define SMEM_BYTES (NSTAGE * STAGE)  // 165888

// ---- device scratch (allocation-free rule) ----
__device__ float g_base[B_ * HID_];
__device__ float g_scores[B_ * NMAX_];
__device__ __nv_bfloat16 g_nodes_b[(size_t)B_ * NMAX_ * H_];    // 67MB
__device__ __nv_bfloat16 g_h1b[(size_t)B_ * NMAX_ * HID_];      // 134MB
__device__ __nv_bfloat16 g_w1b[2][HID_][H_];   // [variant][n][k]
__device__ __nv_bfloat16 g_w2b[HID_][HID_];    // [n][k]

// ---- helpers ----
__device__ __forceinline__ uint32_t smem_u32(const void* p) {
    uint32_t a;
    asm("{ .reg .u64 t; cvta.to.shared.u64 t, %1; cvt.u32.u64 %0, t; }"
        : "=r"(a) : "l"(p));
    return a;
}
__device__ __forceinline__ void cp16(uint32_t s, const void* g) {
    asm volatile("cp.async.cg.shared.global [%0], [%1], 16;"
                 :: "r"(s), "l"(g) : "memory");
}
__device__ __forceinline__ void ldsm4(uint32_t addr, uint32_t* r) {
    asm volatile("ldmatrix.sync.aligned.m8n8.x4.shared.b16 {%0,%1,%2,%3}, [%4];"
                 : "=r"(r[0]), "=r"(r[1]), "=r"(r[2]), "=r"(r[3]) : "r"(addr));
}
__device__ __forceinline__ void mma16816(float* c, const uint32_t* a,
                                         uint32_t b0, uint32_t b1) {
    asm volatile(
        "mma.sync.aligned.m16n8k16.row.col.f32.bf16.bf16.f32 "
        "{%0,%1,%2,%3}, {%4,%5,%6,%7}, {%8,%9}, {%0,%1,%2,%3};"
        : "+f"(c[0]), "+f"(c[1]), "+f"(c[2]), "+f"(c[3])
        : "r"(a[0]), "r"(a[1]), "r"(a[2]), "r"(a[3]), "r"(b0), "r"(b1));
}
__device__ __forceinline__ uint32_t packbf(float lo, float hi) {
    __nv_bfloat162 v = __floats2bfloat162_rn(lo, hi);  // .x=lo(low half)
    return *(uint32_t*)&v;
}

// ============================================================
// Fused prep kernel, block ranges:
//   [0,256)       base (per-batch layer-1 constant, fp32 exact)
//   [256,2304)    nodes fp32 -> bf16 (grid-stride, dead rows skipped)
//   [2304,2560)   W1 transpose+convert: 2 variants x 128 32x32 tiles
//   [2560,2816)   W2 transpose+convert: 256 32x32 tiles
//   [2816,3328)   zero scores
// ============================================================
#define PREP_BLOCKS 3328
__global__ void __launch_bounds__(256) prep_kernel(
    const float* __restrict__ nodes,
    const float* __restrict__ cc,
    const float* __restrict__ W1,
    const float* __restrict__ b1,
    const float* __restrict__ W2,
    const int* __restrict__ dirns,
    const int* __restrict__ ncnt) {
    int blk = blockIdx.x;
    int t = threadIdx.x;
    if (blk < 256) {
        __shared__ float sS[H_];
        __shared__ float sC[C_];
        int b = blk;
        int nc = ncnt[b];
        const float* src = nodes + ((size_t)b * NMAX_ + (size_t)(nc - 1)) * H_;
        sS[t] = src[t];
        if (t < C_) sC[t] = cc[b * C_ + t];
        __syncthreads();
        int off_src = (dirns[b] == 1) ? H_ : 0;
        int j = t;
        float a0 = b1[j], a1 = b1[j + 256];
        const float* Wp = W1 + (size_t)off_src * HID_;
#pragma unroll 8
        for (int k = 0; k < H_; k++) {
            float s = sS[k];
            a0 = fmaf(s, Wp[(size_t)k * HID_ + j], a0);
            a1 = fmaf(s, Wp[(size_t)k * HID_ + j + 256], a1);
        }
        const float* Wc = W1 + (size_t)(2 * H_) * HID_;
#pragma unroll 8
        for (int k = 0; k < C_; k++) {
            float s = sC[k];
            a0 = fmaf(s, Wc[(size_t)k * HID_ + j], a0);
            a1 = fmaf(s, Wc[(size_t)k * HID_ + j + 256], a1);
        }
        g_base[b * HID_ + j] = a0;
        g_base[b * HID_ + j + 256] = a1;
    } else if (blk < 2304) {
        // nodes fp32 -> bf16; skip rows the mask kills (row >= lim, except
        // the src row ncnt-1 which base reads in fp32 anyway).
        const float2* src = (const float2*)nodes;
        uint32_t* dst = (uint32_t*)g_nodes_b;
        int idx = (blk - 256) * 256 + t;
        const int STRIDE = 2048 * 256;
        const int TOTAL = B_ * NMAX_ * (H_ / 2);  // 16777216
#pragma unroll 2
        for (int p = idx; p < TOTAL; p += STRIDE) {
            int grow = p >> 7;              // global row = b*512 + d
            int b = grow >> 9, d = grow & 511;
            if (d >= ncnt[b] - 1) continue; // dead candidate row
            float2 v = src[p];
            dst[p] = packbf(v.x, v.y);
        }
    } else if (blk < 2560) {
        // W1 slice [256k][512n] -> g_w1b[v][n][k] bf16, 32x32 tiles
        __shared__ float s[32][33];
        int u = blk - 2304;
        int v = u >> 7;
        u &= 127;                       // 8 k-tiles x 16 n-tiles
        int k0 = (u >> 4) * 32, n0 = (u & 15) * 32;
        int tx = t & 31, ty = t >> 5;
#pragma unroll
        for (int i = 0; i < 4; i++)
            s[ty + 8 * i][tx] =
                W1[(size_t)(v * 256 + k0 + ty + 8 * i) * HID_ + n0 + tx];
        __syncthreads();
        int n = t & 31, kp0 = t >> 5;   // kp0 in 0..7
#pragma unroll
        for (int i = 0; i < 2; i++) {
            int kp = kp0 + 8 * i;
            uint32_t w = packbf(s[2 * kp][n], s[2 * kp + 1][n]);
            ((uint32_t*)&g_w1b[v][n0 + n][0])[(k0 >> 1) + kp] = w;
        }
    } else if (blk < 2816) {
        // W2 [512k][512n] -> g_w2b[n][k] bf16, 32x32 tiles (16x16 grid)
        __shared__ float s[32][33];
        int u = blk - 2560;
        int k0 = (u >> 4) * 32, n0 = (u & 15) * 32;
        int tx = t & 31, ty = t >> 5;
#pragma unroll
        for (int i = 0; i < 4; i++)
            s[ty + 8 * i][tx] = W2[(size_t)(k0 + ty + 8 * i) * HID_ + n0 + tx];
        __syncthreads();
        int n = t & 31, kp0 = t >> 5;
#pragma unroll
        for (int i = 0; i < 2; i++) {
            int kp = kp0 + 8 * i;
            uint32_t w = packbf(s[2 * kp][n], s[2 * kp + 1][n]);
            ((uint32_t*)&g_w2b[n0 + n][0])[(k0 >> 1) + kp] = w;
        }
    } else {
        int z = blk - 2816;
        g_scores[z * 256 + t] = 0.f;
    }
}

// ============================================================
// bf16 tensor-core GEMM, single pass, dead-tile early exit.
// LAYER=1: h1 = relu(nodes_b @ W1b[n][k] + base), K=256 -> g_h1b (bf16)
// LAYER=2: scores += relu(h1b @ W2b + b2) . W3,   K=512
// CTA 128x256, 512 thr, 16 warps 4Mx4N, warp tile 32x64.
// 3-stage cp.async pipeline, 1 barrier/chunk.
// ============================================================
template <int LAYER>
__global__ void __launch_bounds__(512) gemm_kernel(
    const int* __restrict__ dirns,
    const int* __restrict__ ncnt,
    const float* __restrict__ b2v,
    const float* __restrict__ W3v) {
    extern __shared__ char smdyn[];
    const uint32_t smb = smem_u32(smdyn);
    const int t = threadIdx.x;
    const int b = blockIdx.y;
    const int rt = blockIdx.x >> 1;
    const int nt = blockIdx.x & 1;
    const int d0 = rt * CTA_M, j0 = nt * CTA_N;

    // dead-tile exit: every row in this tile is masked to NEG downstream
    if (d0 >= ncnt[b] - 1) return;

    constexpr int K = (LAYER == 1) ? 256 : 512;
    constexpr int NC = K / KC;

    const __nv_bfloat16* Asrc;  // [row][K]
    const __nv_bfloat16* Bsrc;  // [n][K]
    if (LAYER == 1) {
        Asrc = g_nodes_b + ((size_t)b * NMAX_ + d0) * H_;
        Bsrc = &g_w1b[(dirns[b] == 1) ? 0 : 1][j0][0];
    } else {
        Asrc = g_h1b + ((size_t)b * NMAX_ + d0) * HID_;
        Bsrc = &g_w2b[j0][0];
    }

    auto load_chunk = [&](int c, int stage) {
        uint32_t sA = smb + stage * STAGE;
        uint32_t sB = sA + A_STAGE;
#pragma unroll
        for (int j = 0; j < 2; j++) {  // A: 128 rows x 128B
            int i = t + j * 512;
            int row = i >> 3, q = i & 7;
            const char* g = (const char*)(Asrc + (size_t)row * K + c * KC) + q * 16;
            cp16(sA + row * ROWB + q * 16, g);
        }
#pragma unroll
        for (int j = 0; j < 4; j++) {  // B: 256 rows x 128B
            int i = t + j * 512;
            int row = i >> 3, q = i & 7;
            const char* g = (const char*)(Bsrc + (size_t)row * K + c * KC) + q * 16;
            cp16(sB + row * ROWB + q * 16, g);
        }
        asm volatile("cp.async.commit_group;" ::: "memory");
    };

    load_chunk(0, 0);
    load_chunk(1, 1);

    const int l = t & 31, w = t >> 5, wm = w >> 2, wn = w & 3;
    const uint32_t a_lane =
        (uint32_t)((wm * 32 + (l & 15)) * ROWB + (l >> 4) * 16);
    const uint32_t b_lane =
        (uint32_t)((wn * 64 + (l & 15)) * ROWB + (l >> 4) * 16);

    float cacc[2][8][4];
#pragma unroll
    for (int i = 0; i < 2; i++)
#pragma unroll
        for (int j = 0; j < 8; j++)
#pragma unroll
            for (int q = 0; q < 4; q++) cacc[i][j][q] = 0.f;

    for (int c = 0; c < NC; c++) {
        asm volatile("cp.async.wait_group 1;" ::: "memory");
        __syncthreads();
        if (c + 2 < NC)
            load_chunk(c + 2, (c + 2) % NSTAGE);
        else
            asm volatile("cp.async.commit_group;" ::: "memory");

        const int st = c % NSTAGE;
        const uint32_t sA = smb + st * STAGE, sB = sA + A_STAGE;
#pragma unroll
        for (int ks = 0; ks < 4; ks++) {  // 16 k per step
            uint32_t a[2][4];
#pragma unroll
            for (int mi = 0; mi < 2; mi++)
                ldsm4(sA + a_lane + mi * 16 * ROWB + ks * 32, a[mi]);
#pragma unroll
            for (int nbp = 0; nbp < 4; nbp++) {
                uint32_t bq[4];
                ldsm4(sB + b_lane + nbp * 16 * ROWB + ks * 32, bq);
#pragma unroll
                for (int mi = 0; mi < 2; mi++) {
                    mma16816(cacc[mi][nbp * 2],     a[mi], bq[0], bq[2]);
                    mma16816(cacc[mi][nbp * 2 + 1], a[mi], bq[1], bq[3]);
                }
            }
        }
    }

    // ---------------- epilogue ----------------
    const int lrow = d0 + wm * 32 + (l >> 2);
    const int lcol0 = j0 + wn * 64 + (l & 3) * 2;
    if (LAYER == 1) {
#pragma unroll
        for (int mi = 0; mi < 2; mi++) {
            int r0 = lrow + mi * 16, r1 = r0 + 8;
#pragma unroll
            for (int nj = 0; nj < 8; nj++) {
                int col = lcol0 + nj * 8;
                float2 bs = *(const float2*)&g_base[b * HID_ + col];
                uint32_t v0 = packbf(fmaxf(cacc[mi][nj][0] + bs.x, 0.f),
                                     fmaxf(cacc[mi][nj][1] + bs.y, 0.f));
                uint32_t v1 = packbf(fmaxf(cacc[mi][nj][2] + bs.x, 0.f),
                                     fmaxf(cacc[mi][nj][3] + bs.y, 0.f));
                ((uint32_t*)g_h1b)[(((size_t)b * NMAX_ + r0) * HID_ + col) >> 1] = v0;
                ((uint32_t*)g_h1b)[(((size_t)b * NMAX_ + r1) * HID_ + col) >> 1] = v1;
            }
        }
    } else {
        float s[2][2] = {{0.f, 0.f}, {0.f, 0.f}};
#pragma unroll
        for (int mi = 0; mi < 2; mi++)
#pragma unroll
            for (int nj = 0; nj < 8; nj++) {
                int col = lcol0 + nj * 8;
                float2 bb = *(const float2*)&b2v[col];
                float2 ww = *(const float2*)&W3v[col];
                s[mi][0] += fmaxf(cacc[mi][nj][0] + bb.x, 0.f) * ww.x +
                            fmaxf(cacc[mi][nj][1] + bb.y, 0.f) * ww.y;
                s[mi][1] += fmaxf(cacc[mi][nj][2] + bb.x, 0.f) * ww.x +
                            fmaxf(cacc[mi][nj][3] + bb.y, 0.f) * ww.y;
            }
#pragma unroll
        for (int mi = 0; mi < 2; mi++)
#pragma unroll
            for (int h = 0; h < 2; h++) {
                float v = s[mi][h];
                v += __shfl_xor_sync(0xffffffffu, v, 1);
                v += __shfl_xor_sync(0xffffffffu, v, 2);
                if ((l & 3) == 0)
                    atomicAdd(&g_scores[b * NMAX_ + lrow + mi * 16 + h * 8], v);
            }
    }
}

// ============================================================
// loss: masked log-softmax -> per-batch loss (b3 cancels)
// ============================================================
__global__ void loss_kernel(const int* __restrict__ ncnt,
                            const int* __restrict__ dests,
                            float* __restrict__ out) {
    __shared__ float red[256];
    int b = blockIdx.x, t = threadIdx.x;
    int lim = ncnt[b] - 1;
    const float* sc = g_scores + b * NMAX_;
    float s1 = (t < lim) ? sc[t] : NEGV;
    int d2 = t + 256;
    float s2 = (d2 < lim) ? sc[d2] : NEGV;

    float m = fmaxf(s1, s2);
    red[t] = m;
    __syncthreads();
    for (int o = 128; o; o >>= 1) {
        if (t < o) red[t] = fmaxf(red[t], red[t + o]);
        __syncthreads();
    }
    float mx = red[0];
    __syncthreads();
    float e = expf(s1 - mx) + expf(s2 - mx);
    red[t] = e;
    __syncthreads();
    for (int o = 128; o; o >>= 1) {
        if (t < o) red[t] += red[t + o];
        __syncthreads();
    }
    if (t == 0) {
        float lse = mx + logf(red[0]);
        out[b] = lse - sc[dests[b]];
    }
}

// ============================================================
extern "C" void kernel_launch(void* const* d_in, const int* in_sizes, int n_in,
                              void* d_out, int out_size) {
    const float* nodes = (const float*)d_in[0];
    const float* cc    = (const float*)d_in[1];
    const float* W1    = (const float*)d_in[2];
    const float* b1    = (const float*)d_in[3];
    const float* W2    = (const float*)d_in[4];
    const float* b2    = (const float*)d_in[5];
    const float* W3    = (const float*)d_in[6];
    // d_in[7] = b3 (cancels in log_softmax)
    const int* dirns   = (const int*)d_in[8];
    const int* ncnt    = (const int*)d_in[9];
    const int* dests   = (const int*)d_in[10];
    float* out = (float*)d_out;

    cudaFuncSetAttribute(gemm_kernel<1>,
                         cudaFuncAttributeMaxDynamicSharedMemorySize, SMEM_BYTES);
    cudaFuncSetAttribute(gemm_kernel<2>,
                         cudaFuncAttributeMaxDynamicSharedMemorySize, SMEM_BYTES);

    prep_kernel<<<PREP_BLOCKS, 256>>>(nodes, cc, W1, b1, W2, dirns, ncnt);

    dim3 grid(8, B_);
    gemm_kernel<1><<<grid, 512, SMEM_BYTES>>>(dirns, ncnt, b2, W3);
    gemm_kernel<2><<<grid, 512, SMEM_BYTES>>>(dirns, ncnt, b2, W3);
    loss_kernel<<<B_, 256>>>(ncnt, dests, out);
}